// round 6
// baseline (speedup 1.0000x reference)
#include <cuda_runtime.h>

// PairwiseL1Loss: x,y [256][4096] fp32.
// out[i] = -(1/D^2) * sum_j (sum_k|x_i-x_j|) * (sum_k|y_i-y_j|)
//
// Identity: sum_k|x_i-x_j| = 2*sum_k max(x_ik,x_jk) - S_i - S_j.
//
// PS : row sums Sx[256], Sy[256].
// PA : 32x32 pair tiles, upper-tri (36 of 64), k-split x16 -> grid 576,
//      occ 4 -> single wave. 2x2 reg tile/thread, swizzled smem.
// E1 : per tile-slab: sum k-chunks, identity, product, row sums + col partials.
// E2 : final combine, scale, negate.

#define BB 256
#define DD 4096
#define TILE 32
#define NT (BB / TILE)                 // 8 tiles per side
#define NPT 36                         // upper-tri tile count
#define KSPLIT 16
#define KPER (DD / KSPLIT)             // 256 k per CTA
#define KC 32                          // smem stage depth (rows exactly 128B)
#define NSTAGE (KPER / KC)             // 8

// [pt][kc][row*16 + colpair] : {mx0, my0, mx1, my1}
__device__ float4 g_part[NPT * KSPLIT * TILE * (TILE / 2)];   // ~4.7MB
__device__ float  g_final[BB * NT];                            // row-sum contribs
__device__ float  g_colpart[NPT * 4 * TILE];                   // col partials per 8-row seg
__device__ float  g_Sx[BB];
__device__ float  g_Sy[BB];

__constant__ int c_bi[NPT] = {0,0,0,0,0,0,0,0, 1,1,1,1,1,1,1, 2,2,2,2,2,2,
                              3,3,3,3,3, 4,4,4,4, 5,5,5, 6,6, 7};
__constant__ int c_bj[NPT] = {0,1,2,3,4,5,6,7, 1,2,3,4,5,6,7, 2,3,4,5,6,7,
                              3,4,5,6,7, 4,5,6,7, 5,6,7, 6,7, 7};

#define MAX4(acc, u, v)                          \
    acc += fmaxf((u).x, (v).x);                  \
    acc += fmaxf((u).y, (v).y);                  \
    acc += fmaxf((u).z, (v).z);                  \
    acc += fmaxf((u).w, (v).w);

// ---------- PS: row sums ----------
__global__ void ps_kernel(const float* __restrict__ x,
                          const float* __restrict__ y)
{
    const int row = blockIdx.x;
    const int tid = threadIdx.x;
    float sx = 0.f, sy = 0.f;
    const float4* px = (const float4*)(x + (size_t)row * DD);
    const float4* py = (const float4*)(y + (size_t)row * DD);
    #pragma unroll
    for (int v = tid; v < DD / 4; v += 128) {
        const float4 a = px[v];
        const float4 b = py[v];
        sx += (a.x + a.y) + (a.z + a.w);
        sy += (b.x + b.y) + (b.z + b.w);
    }
    #pragma unroll
    for (int off = 16; off > 0; off >>= 1) {
        sx += __shfl_xor_sync(0xffffffffu, sx, off);
        sy += __shfl_xor_sync(0xffffffffu, sy, off);
    }
    __shared__ float wx[4], wy[4];
    if ((tid & 31) == 0) { wx[tid >> 5] = sx; wy[tid >> 5] = sy; }
    __syncthreads();
    if (tid == 0) {
        g_Sx[row] = (wx[0] + wx[1]) + (wx[2] + wx[3]);
        g_Sy[row] = (wy[0] + wy[1]) + (wy[2] + wy[3]);
    }
}

// ---------- PA: max-sum pair tiles ----------
__global__ __launch_bounds__(256, 4)
void pa_kernel(const float* __restrict__ x, const float* __restrict__ y)
{
    // [row][8 quads], quad swizzled by (row>>1)&7
    __shared__ float4 sxi[TILE * 8];
    __shared__ float4 sxj[TILE * 8];
    __shared__ float4 syi[TILE * 8];
    __shared__ float4 syj[TILE * 8];

    const int pt = blockIdx.x / KSPLIT;
    const int kc = blockIdx.x % KSPLIT;
    const int bi = c_bi[pt], bj = c_bj[pt];
    const int iBase = bi * TILE, jBase = bj * TILE;
    const int tid = threadIdx.x;
    const int ti = tid >> 4;           // 0..15 -> rows 2ti, 2ti+1
    const int tj = tid & 15;           // 0..15 -> cols 2tj, 2tj+1

    float mx00 = 0.f, mx01 = 0.f, mx10 = 0.f, mx11 = 0.f;
    float my00 = 0.f, my01 = 0.f, my10 = 0.f, my11 = 0.f;

    const int tik = ti & 7;
    const int tjk = tj & 7;
    // staging indices: one float4 per thread per array
    const int sr = tid >> 3;           // 0..31
    const int sq = tid & 7;
    const int ssw = sr * 8 + (sq ^ ((sr >> 1) & 7));

    for (int st = 0; st < NSTAGE; st++) {
        const int kBase = kc * KPER + st * KC;
        __syncthreads();
        {
            const size_t offI = (size_t)(iBase + sr) * DD + kBase;
            const size_t offJ = (size_t)(jBase + sr) * DD + kBase;
            sxi[ssw] = ((const float4*)(x + offI))[sq];
            sxj[ssw] = ((const float4*)(x + offJ))[sq];
            syi[ssw] = ((const float4*)(y + offI))[sq];
            syj[ssw] = ((const float4*)(y + offJ))[sq];
        }
        __syncthreads();

        #pragma unroll
        for (int kq = 0; kq < 8; kq++) {
            const int qi = kq ^ tik;
            const int qj = kq ^ tjk;
            {
                const float4 u0 = sxi[(2 * ti    ) * 8 + qi];
                const float4 u1 = sxi[(2 * ti + 1) * 8 + qi];
                const float4 v0 = sxj[(2 * tj    ) * 8 + qj];
                const float4 v1 = sxj[(2 * tj + 1) * 8 + qj];
                MAX4(mx00, u0, v0); MAX4(mx01, u0, v1);
                MAX4(mx10, u1, v0); MAX4(mx11, u1, v1);
            }
            {
                const float4 u0 = syi[(2 * ti    ) * 8 + qi];
                const float4 u1 = syi[(2 * ti + 1) * 8 + qi];
                const float4 v0 = syj[(2 * tj    ) * 8 + qj];
                const float4 v1 = syj[(2 * tj + 1) * 8 + qj];
                MAX4(my00, u0, v0); MAX4(my01, u0, v1);
                MAX4(my10, u1, v0); MAX4(my11, u1, v1);
            }
        }
    }

    // [pt][kc][row*16 + colpair] = {mx(c0), my(c0), mx(c1), my(c1)}
    float4* gp = g_part + ((size_t)pt * KSPLIT + kc) * (TILE * (TILE / 2));
    gp[(2 * ti    ) * 16 + tj] = make_float4(mx00, my00, mx01, my01);
    gp[(2 * ti + 1) * 16 + tj] = make_float4(mx10, my10, mx11, my11);
}

// ---------- E1: k-chunk sum + identity + product + row/col reductions ----------
// grid = NPT*4, block = 128. Each CTA: one 8-row slab of one tile.
__global__ void e1_kernel()
{
    __shared__ float sp[8][TILE + 1];

    const int pt  = blockIdx.x >> 2;
    const int seg = blockIdx.x & 3;
    const int bi = c_bi[pt], bj = c_bj[pt];
    const int t = threadIdx.x;
    const int rloc = t >> 4;           // 0..7
    const int cp   = t & 15;           // col pair 0..15
    const int r = seg * 8 + rloc;
    const int ig = bi * TILE + r;
    const int j0 = bj * TILE + 2 * cp;

    const float4* gp = g_part + (size_t)pt * KSPLIT * (TILE * (TILE / 2))
                              + r * 16 + cp;
    float4 m = make_float4(0.f, 0.f, 0.f, 0.f);
    #pragma unroll
    for (int kcc = 0; kcc < KSPLIT; kcc++) {
        const float4 v = gp[(size_t)kcc * (TILE * (TILE / 2))];
        m.x += v.x; m.y += v.y; m.z += v.z; m.w += v.w;
    }
    const float Sxi = g_Sx[ig], Syi = g_Sy[ig];
    const float sx0 = 2.0f * m.x - Sxi - g_Sx[j0];
    const float sy0 = 2.0f * m.y - Syi - g_Sy[j0];
    const float sx1 = 2.0f * m.z - Sxi - g_Sx[j0 + 1];
    const float sy1 = 2.0f * m.w - Syi - g_Sy[j0 + 1];
    const float p0 = sx0 * sy0;
    const float p1 = sx1 * sy1;

    // row sum over 16 lanes (cp) of this rloc
    float rs = p0 + p1;
    #pragma unroll
    for (int off = 8; off > 0; off >>= 1)
        rs += __shfl_xor_sync(0xffffffffu, rs, off);
    if (cp == 0)
        g_final[ig * NT + bj] = rs;

    // col partials over the 8 rows of this slab
    sp[rloc][2 * cp]     = p0;
    sp[rloc][2 * cp + 1] = p1;
    __syncthreads();
    if (t < TILE) {
        float cs = 0.f;
        #pragma unroll
        for (int rr = 0; rr < 8; rr++) cs += sp[rr][t];
        g_colpart[(pt * 4 + seg) * TILE + t] = cs;
    }
}

// ---------- E2: final combine ----------
__global__ void e2_kernel(float* __restrict__ out)
{
    const int i = threadIdx.x;          // 256 threads, 1 block
    const int bi = i >> 5;              // tile of row i
    const int c  = i & 31;              // col within tile
    float s = 0.f;
    // row-sum contributions: tiles (bi, t), t >= bi
    #pragma unroll
    for (int t2 = 0; t2 < NT; t2++)
        if (t2 >= bi) s += g_final[i * NT + t2];
    // col-sum contributions: tiles (a, bi), a < bi
    for (int a = 0; a < bi; a++) {
        const int pt = a * NT - (a * (a - 1)) / 2 + (bi - a);
        #pragma unroll
        for (int seg = 0; seg < 4; seg++)
            s += g_colpart[(pt * 4 + seg) * TILE + c];
    }
    out[i] = -s * (1.0f / ((float)DD * (float)DD));
}

extern "C" void kernel_launch(void* const* d_in, const int* in_sizes, int n_in,
                              void* d_out, int out_size)
{
    const float* x = (const float*)d_in[0];
    const float* y = (const float*)d_in[1];
    float* out = (float*)d_out;

    ps_kernel<<<BB, 128>>>(x, y);
    pa_kernel<<<NPT * KSPLIT, 256>>>(x, y);
    e1_kernel<<<NPT * 4, 128>>>();
    e2_kernel<<<1, 256>>>(out);
}

// round 7
// speedup vs baseline: 1.0617x; 1.0617x over previous
#include <cuda_runtime.h>
#include <cstdint>

// PairwiseL1Loss: x,y [256][4096] fp32.
// out[i] = -(1/D^2) * sum_j (sum_k|x_i-x_j|) * (sum_k|y_i-y_j|)
// Identity: sum_k|x_i-x_j| = 2*sum_k max(x_ik,x_jk) - S_i - S_j.
//
// PS : row sums Sx[256], Sy[256].
// PA : 32x32 pair tiles, upper-tri (36), k-split x16 -> grid 576, occ 4 ->
//      single wave. cp.async double-buffered staging, packed f32x2 accum.
// E1 : one CTA per tile: k-chunk sum + identity + product + row sums +
//      complete col sums.
// E2 : final combine, scale, negate.

#define BB 256
#define DD 4096
#define TILE 32
#define NT (BB / TILE)                 // 8
#define NPT 36                         // upper-tri tiles
#define KSPLIT 16
#define KPER (DD / KSPLIT)             // 256
#define KC 32                          // floats per stage row (128B)
#define NSTAGE (KPER / KC)             // 8

// [pt][kc][row*16 + colpair] : {mx0, my0, mx1, my1}
__device__ float4 g_part[NPT * KSPLIT * TILE * (TILE / 2)];   // ~4.7MB
__device__ float  g_final[BB * NT];
__device__ float  g_colpart[NPT * TILE];
__device__ float  g_Sx[BB];
__device__ float  g_Sy[BB];

__constant__ int c_bi[NPT] = {0,0,0,0,0,0,0,0, 1,1,1,1,1,1,1, 2,2,2,2,2,2,
                              3,3,3,3,3, 4,4,4,4, 5,5,5, 6,6, 7};
__constant__ int c_bj[NPT] = {0,1,2,3,4,5,6,7, 1,2,3,4,5,6,7, 2,3,4,5,6,7,
                              3,4,5,6,7, 4,5,6,7, 5,6,7, 6,7, 7};

// packed f32x2 accumulate: acc += (max components pairwise-summed)
__device__ __forceinline__ void maxacc(unsigned long long& acc,
                                       const float4 u, const float4 v)
{
    const float m0 = fmaxf(u.x, v.x);
    const float m1 = fmaxf(u.y, v.y);
    const float m2 = fmaxf(u.z, v.z);
    const float m3 = fmaxf(u.w, v.w);
    unsigned long long p01, p23, s;
    asm("mov.b64 %0, {%1, %2};" : "=l"(p01) : "f"(m0), "f"(m1));
    asm("mov.b64 %0, {%1, %2};" : "=l"(p23) : "f"(m2), "f"(m3));
    asm("add.rn.f32x2 %0, %1, %2;" : "=l"(s) : "l"(p01), "l"(p23));
    asm("add.rn.f32x2 %0, %0, %1;" : "+l"(acc) : "l"(s));
}

__device__ __forceinline__ float unpack_sum(unsigned long long acc)
{
    float lo, hi;
    asm("mov.b64 {%0, %1}, %2;" : "=f"(lo), "=f"(hi) : "l"(acc));
    return lo + hi;
}

// ---------- PS: row sums ----------
__global__ void ps_kernel(const float* __restrict__ x,
                          const float* __restrict__ y)
{
    const int row = blockIdx.x;
    const int tid = threadIdx.x;
    float sx = 0.f, sy = 0.f;
    const float4* px = (const float4*)(x + (size_t)row * DD);
    const float4* py = (const float4*)(y + (size_t)row * DD);
    #pragma unroll
    for (int v = tid; v < DD / 4; v += 128) {
        const float4 a = px[v];
        const float4 b = py[v];
        sx += (a.x + a.y) + (a.z + a.w);
        sy += (b.x + b.y) + (b.z + b.w);
    }
    #pragma unroll
    for (int off = 16; off > 0; off >>= 1) {
        sx += __shfl_xor_sync(0xffffffffu, sx, off);
        sy += __shfl_xor_sync(0xffffffffu, sy, off);
    }
    __shared__ float wx[4], wy[4];
    if ((tid & 31) == 0) { wx[tid >> 5] = sx; wy[tid >> 5] = sy; }
    __syncthreads();
    if (tid == 0) {
        g_Sx[row] = (wx[0] + wx[1]) + (wx[2] + wx[3]);
        g_Sy[row] = (wy[0] + wy[1]) + (wy[2] + wy[3]);
    }
}

// ---------- PA: max-sum pair tiles ----------
__global__ __launch_bounds__(256, 4)
void pa_kernel(const float* __restrict__ x, const float* __restrict__ y)
{
    // 2 buffers x 4 arrays x (32 rows x 8 quads) float4, swizzle q^((r>>1)&7)
    __shared__ float4 sbuf[2][4][TILE * 8];

    const int pt = blockIdx.x / KSPLIT;
    const int kc = blockIdx.x % KSPLIT;
    const int bi = c_bi[pt], bj = c_bj[pt];
    const int iBase = bi * TILE, jBase = bj * TILE;
    const int tid = threadIdx.x;
    const int ti = tid >> 4;
    const int tj = tid & 15;
    const int tik = ti & 7;
    const int tjk = tj & 7;

    // staging: one float4 per thread per array
    const int sr = tid >> 3;           // 0..31
    const int sq = tid & 7;
    const int ssw = sr * 8 + (sq ^ ((sr >> 1) & 7));

    const float* srcXI = x + (size_t)(iBase + sr) * DD + kc * KPER + sq * 4;
    const float* srcXJ = x + (size_t)(jBase + sr) * DD + kc * KPER + sq * 4;
    const float* srcYI = y + (size_t)(iBase + sr) * DD + kc * KPER + sq * 4;
    const float* srcYJ = y + (size_t)(jBase + sr) * DD + kc * KPER + sq * 4;

    unsigned long long mx00 = 0ull, mx01 = 0ull, mx10 = 0ull, mx11 = 0ull;
    unsigned long long my00 = 0ull, my01 = 0ull, my10 = 0ull, my11 = 0ull;

    // prefetch stage 0
    {
        const uint32_t d0 = (uint32_t)__cvta_generic_to_shared(&sbuf[0][0][ssw]);
        const uint32_t d1 = (uint32_t)__cvta_generic_to_shared(&sbuf[0][1][ssw]);
        const uint32_t d2 = (uint32_t)__cvta_generic_to_shared(&sbuf[0][2][ssw]);
        const uint32_t d3 = (uint32_t)__cvta_generic_to_shared(&sbuf[0][3][ssw]);
        asm volatile("cp.async.cg.shared.global [%0], [%1], 16;" :: "r"(d0), "l"(srcXI));
        asm volatile("cp.async.cg.shared.global [%0], [%1], 16;" :: "r"(d1), "l"(srcXJ));
        asm volatile("cp.async.cg.shared.global [%0], [%1], 16;" :: "r"(d2), "l"(srcYI));
        asm volatile("cp.async.cg.shared.global [%0], [%1], 16;" :: "r"(d3), "l"(srcYJ));
        asm volatile("cp.async.commit_group;");
    }

    for (int st = 0; st < NSTAGE; st++) {
        asm volatile("cp.async.wait_group 0;");
        __syncthreads();

        if (st + 1 < NSTAGE) {
            const int nb = (st + 1) & 1;
            const int koff = (st + 1) * KC;
            const uint32_t d0 = (uint32_t)__cvta_generic_to_shared(&sbuf[nb][0][ssw]);
            const uint32_t d1 = (uint32_t)__cvta_generic_to_shared(&sbuf[nb][1][ssw]);
            const uint32_t d2 = (uint32_t)__cvta_generic_to_shared(&sbuf[nb][2][ssw]);
            const uint32_t d3 = (uint32_t)__cvta_generic_to_shared(&sbuf[nb][3][ssw]);
            asm volatile("cp.async.cg.shared.global [%0], [%1], 16;" :: "r"(d0), "l"(srcXI + koff));
            asm volatile("cp.async.cg.shared.global [%0], [%1], 16;" :: "r"(d1), "l"(srcXJ + koff));
            asm volatile("cp.async.cg.shared.global [%0], [%1], 16;" :: "r"(d2), "l"(srcYI + koff));
            asm volatile("cp.async.cg.shared.global [%0], [%1], 16;" :: "r"(d3), "l"(srcYJ + koff));
            asm volatile("cp.async.commit_group;");
        }

        const float4* bxi = sbuf[st & 1][0];
        const float4* bxj = sbuf[st & 1][1];
        const float4* byi = sbuf[st & 1][2];
        const float4* byj = sbuf[st & 1][3];

        #pragma unroll
        for (int kq = 0; kq < 8; kq++) {
            const int qi = kq ^ tik;
            const int qj = kq ^ tjk;
            {
                const float4 u0 = bxi[(2 * ti    ) * 8 + qi];
                const float4 u1 = bxi[(2 * ti + 1) * 8 + qi];
                const float4 v0 = bxj[(2 * tj    ) * 8 + qj];
                const float4 v1 = bxj[(2 * tj + 1) * 8 + qj];
                maxacc(mx00, u0, v0); maxacc(mx01, u0, v1);
                maxacc(mx10, u1, v0); maxacc(mx11, u1, v1);
            }
            {
                const float4 u0 = byi[(2 * ti    ) * 8 + qi];
                const float4 u1 = byi[(2 * ti + 1) * 8 + qi];
                const float4 v0 = byj[(2 * tj    ) * 8 + qj];
                const float4 v1 = byj[(2 * tj + 1) * 8 + qj];
                maxacc(my00, u0, v0); maxacc(my01, u0, v1);
                maxacc(my10, u1, v0); maxacc(my11, u1, v1);
            }
        }
    }

    float4* gp = g_part + ((size_t)pt * KSPLIT + kc) * (TILE * (TILE / 2));
    gp[(2 * ti    ) * 16 + tj] = make_float4(unpack_sum(mx00), unpack_sum(my00),
                                             unpack_sum(mx01), unpack_sum(my01));
    gp[(2 * ti + 1) * 16 + tj] = make_float4(unpack_sum(mx10), unpack_sum(my10),
                                             unpack_sum(mx11), unpack_sum(my11));
}

// ---------- E1: per tile: k-sum + identity + product + row & col sums ----------
// grid = NPT, block = 256 (each thread handles 2 of 512 (row,colpair) items)
__global__ void e1_kernel()
{
    __shared__ float sp[TILE][TILE + 1];

    const int pt = blockIdx.x;
    const int bi = c_bi[pt], bj = c_bj[pt];
    const int t = threadIdx.x;
    const float4* gpt = g_part + (size_t)pt * KSPLIT * (TILE * (TILE / 2));

    #pragma unroll
    for (int half = 0; half < 2; half++) {
        const int item = t + 256 * half;
        const int r  = item >> 4;
        const int cp = item & 15;
        const int ig = bi * TILE + r;
        const int j0 = bj * TILE + 2 * cp;

        const float4* gp = gpt + r * 16 + cp;
        float4 m = make_float4(0.f, 0.f, 0.f, 0.f);
        #pragma unroll
        for (int kcc = 0; kcc < KSPLIT; kcc++) {
            const float4 v = gp[(size_t)kcc * (TILE * (TILE / 2))];
            m.x += v.x; m.y += v.y; m.z += v.z; m.w += v.w;
        }
        const float Sxi = g_Sx[ig], Syi = g_Sy[ig];
        const float sx0 = 2.0f * m.x - Sxi - g_Sx[j0];
        const float sy0 = 2.0f * m.y - Syi - g_Sy[j0];
        const float sx1 = 2.0f * m.z - Sxi - g_Sx[j0 + 1];
        const float sy1 = 2.0f * m.w - Syi - g_Sy[j0 + 1];
        const float p0 = sx0 * sy0;
        const float p1 = sx1 * sy1;

        sp[r][2 * cp]     = p0;
        sp[r][2 * cp + 1] = p1;

        // row sum across the 16 cp-lanes (consecutive lanes share r)
        float rs = p0 + p1;
        #pragma unroll
        for (int off = 8; off > 0; off >>= 1)
            rs += __shfl_xor_sync(0xffffffffu, rs, off);
        if (cp == 0)
            g_final[ig * NT + bj] = rs;
    }
    __syncthreads();

    if (t < TILE) {
        float cs = 0.f;
        #pragma unroll
        for (int rr = 0; rr < TILE; rr++) cs += sp[rr][t];
        g_colpart[pt * TILE + t] = cs;
    }
}

// ---------- E2: final combine ----------
__global__ void e2_kernel(float* __restrict__ out)
{
    const int i = threadIdx.x;          // 256 threads, 1 block
    const int bi = i >> 5;
    const int c  = i & 31;
    float s = 0.f;
    #pragma unroll
    for (int t2 = 0; t2 < NT; t2++)
        if (t2 >= bi) s += g_final[i * NT + t2];
    for (int a = 0; a < bi; a++) {
        const int pt = a * NT - (a * (a - 1)) / 2 + (bi - a);
        s += g_colpart[pt * TILE + c];
    }
    out[i] = -s * (1.0f / ((float)DD * (float)DD));
}

extern "C" void kernel_launch(void* const* d_in, const int* in_sizes, int n_in,
                              void* d_out, int out_size)
{
    const float* x = (const float*)d_in[0];
    const float* y = (const float*)d_in[1];
    float* out = (float*)d_out;

    ps_kernel<<<BB, 128>>>(x, y);
    pa_kernel<<<NPT * KSPLIT, 256>>>(x, y);
    e1_kernel<<<NPT, 256>>>();
    e2_kernel<<<1, 256>>>(out);
}

// round 8
// speedup vs baseline: 1.5010x; 1.4138x over previous
#include <cuda_runtime.h>
#include <cuda_fp16.h>
#include <cstdint>

// PairwiseL1Loss: x,y [256][4096] fp32.
// out[i] = -(1/D^2) * sum_j (sum_k|x_i-x_j|) * (sum_k|y_i-y_j|)
// Identity: sum_k|x_i-x_j| = 2*sum_k max(x_ik,x_jk) - S_i - S_j  (on fp16-
// rounded inputs; S computed from the SAME rounded values -> identity exact).
//
// CONV: fp32 -> fp16 copies of x,y + row sums (f32) of the rounded values.
// PA  : 32x32 pair tiles, upper-tri (36), k-split x16 -> grid 576, occ 4.
//       cp.async double-buffered fp16 staging; __hmax2/__hadd2 (2 pairs/instr),
//       per-stage drain of fp16 accumulators into f32.
// E1F : per-tile k-chunk sum + identity + product + row/col sums; last CTA
//       (int-atomic counter) performs the final combine. 3 launches total.

#define BB 256
#define DD 4096
#define TILE 32
#define NT (BB / TILE)                 // 8
#define NPT 36                         // upper-tri tiles
#define KSPLIT 16
#define KPER (DD / KSPLIT)             // 256
#define KC 64                          // halfs per stage row (128B)
#define NSTAGE (KPER / KC)             // 4

__device__ __half g_hx[BB * DD];       // 2MB
__device__ __half g_hy[BB * DD];       // 2MB
__device__ float4 g_part[NPT * KSPLIT * TILE * (TILE / 2)];   // ~4.7MB
__device__ float  g_final[BB * NT];
__device__ float  g_colpart[NPT * TILE];
__device__ float  g_Sx[BB];
__device__ float  g_Sy[BB];
__device__ unsigned int g_cnt = 0;

__constant__ int c_bi[NPT] = {0,0,0,0,0,0,0,0, 1,1,1,1,1,1,1, 2,2,2,2,2,2,
                              3,3,3,3,3, 4,4,4,4, 5,5,5, 6,6, 7};
__constant__ int c_bj[NPT] = {0,1,2,3,4,5,6,7, 1,2,3,4,5,6,7, 2,3,4,5,6,7,
                              3,4,5,6,7, 4,5,6,7, 5,6,7, 6,7, 7};

// acc += sum of 4 half2 maxes of 8-half vectors u,v  (4 HMNMX2 + 4 HADD2)
__device__ __forceinline__ __half2 acc8(__half2 acc, const uint4 u, const uint4 v)
{
    const __half2* a = (const __half2*)&u;
    const __half2* b = (const __half2*)&v;
    const __half2 m0 = __hmax2(a[0], b[0]);
    const __half2 m1 = __hmax2(a[1], b[1]);
    const __half2 m2 = __hmax2(a[2], b[2]);
    const __half2 m3 = __hmax2(a[3], b[3]);
    return __hadd2(acc, __hadd2(__hadd2(m0, m1), __hadd2(m2, m3)));
}

__device__ __forceinline__ float drain(__half2 h)
{
    const float2 f = __half22float2(h);
    return f.x + f.y;
}

// ---------- CONV: fp16 copies + row sums of rounded values ----------
__global__ void conv_kernel(const float* __restrict__ x,
                            const float* __restrict__ y)
{
    const int row = blockIdx.x;
    const int tid = threadIdx.x;       // block 128
    const float4* px = (const float4*)(x + (size_t)row * DD);
    const float4* py = (const float4*)(y + (size_t)row * DD);
    uint2* hx = (uint2*)(g_hx + (size_t)row * DD);
    uint2* hy = (uint2*)(g_hy + (size_t)row * DD);
    float sx = 0.f, sy = 0.f;
    for (int v = tid; v < DD / 4; v += 128) {
        const float4 a = px[v];
        const float4 b = py[v];
        const __half2 ha0 = __floats2half2_rn(a.x, a.y);
        const __half2 ha1 = __floats2half2_rn(a.z, a.w);
        const __half2 hb0 = __floats2half2_rn(b.x, b.y);
        const __half2 hb1 = __floats2half2_rn(b.z, b.w);
        uint2 ua, ub;
        ua.x = *(const unsigned*)&ha0;  ua.y = *(const unsigned*)&ha1;
        ub.x = *(const unsigned*)&hb0;  ub.y = *(const unsigned*)&hb1;
        hx[v] = ua;
        hy[v] = ub;
        sx += drain(ha0) + drain(ha1);
        sy += drain(hb0) + drain(hb1);
    }
    #pragma unroll
    for (int off = 16; off > 0; off >>= 1) {
        sx += __shfl_xor_sync(0xffffffffu, sx, off);
        sy += __shfl_xor_sync(0xffffffffu, sy, off);
    }
    __shared__ float wx[4], wy[4];
    if ((tid & 31) == 0) { wx[tid >> 5] = sx; wy[tid >> 5] = sy; }
    __syncthreads();
    if (tid == 0) {
        g_Sx[row] = (wx[0] + wx[1]) + (wx[2] + wx[3]);
        g_Sy[row] = (wy[0] + wy[1]) + (wy[2] + wy[3]);
    }
}

// ---------- PA: fp16 max-sum pair tiles ----------
__global__ __launch_bounds__(256, 4)
void pa_kernel()
{
    // 2 buffers x 4 arrays x (32 rows x 8 quads of 8 halfs) = 32KB
    __shared__ uint4 sbuf[2][4][TILE * 8];

    const int pt = blockIdx.x / KSPLIT;
    const int kc = blockIdx.x % KSPLIT;
    const int bi = c_bi[pt], bj = c_bj[pt];
    const int tid = threadIdx.x;
    const int ti = tid >> 4;
    const int tj = tid & 15;
    const int tik = ti & 7;
    const int tjk = tj & 7;

    const int sr = tid >> 3;           // 0..31
    const int sq = tid & 7;
    const int ssw = sr * 8 + (sq ^ ((sr >> 1) & 7));

    const __half* srcXI = g_hx + (size_t)(bi * TILE + sr) * DD + kc * KPER + sq * 8;
    const __half* srcXJ = g_hx + (size_t)(bj * TILE + sr) * DD + kc * KPER + sq * 8;
    const __half* srcYI = g_hy + (size_t)(bi * TILE + sr) * DD + kc * KPER + sq * 8;
    const __half* srcYJ = g_hy + (size_t)(bj * TILE + sr) * DD + kc * KPER + sq * 8;

    const __half2 hz = __floats2half2_rn(0.f, 0.f);
    __half2 hx00 = hz, hx01 = hz, hx10 = hz, hx11 = hz;
    __half2 hy00 = hz, hy01 = hz, hy10 = hz, hy11 = hz;
    float fx00 = 0.f, fx01 = 0.f, fx10 = 0.f, fx11 = 0.f;
    float fy00 = 0.f, fy01 = 0.f, fy10 = 0.f, fy11 = 0.f;

    // prefetch stage 0
    {
        const uint32_t d0 = (uint32_t)__cvta_generic_to_shared(&sbuf[0][0][ssw]);
        const uint32_t d1 = (uint32_t)__cvta_generic_to_shared(&sbuf[0][1][ssw]);
        const uint32_t d2 = (uint32_t)__cvta_generic_to_shared(&sbuf[0][2][ssw]);
        const uint32_t d3 = (uint32_t)__cvta_generic_to_shared(&sbuf[0][3][ssw]);
        asm volatile("cp.async.cg.shared.global [%0], [%1], 16;" :: "r"(d0), "l"(srcXI));
        asm volatile("cp.async.cg.shared.global [%0], [%1], 16;" :: "r"(d1), "l"(srcXJ));
        asm volatile("cp.async.cg.shared.global [%0], [%1], 16;" :: "r"(d2), "l"(srcYI));
        asm volatile("cp.async.cg.shared.global [%0], [%1], 16;" :: "r"(d3), "l"(srcYJ));
        asm volatile("cp.async.commit_group;");
    }

    #pragma unroll
    for (int st = 0; st < NSTAGE; st++) {
        asm volatile("cp.async.wait_group 0;");
        __syncthreads();

        if (st + 1 < NSTAGE) {
            const int nb = (st + 1) & 1;
            const int koff = (st + 1) * KC;       // halfs
            const uint32_t d0 = (uint32_t)__cvta_generic_to_shared(&sbuf[nb][0][ssw]);
            const uint32_t d1 = (uint32_t)__cvta_generic_to_shared(&sbuf[nb][1][ssw]);
            const uint32_t d2 = (uint32_t)__cvta_generic_to_shared(&sbuf[nb][2][ssw]);
            const uint32_t d3 = (uint32_t)__cvta_generic_to_shared(&sbuf[nb][3][ssw]);
            asm volatile("cp.async.cg.shared.global [%0], [%1], 16;" :: "r"(d0), "l"(srcXI + koff));
            asm volatile("cp.async.cg.shared.global [%0], [%1], 16;" :: "r"(d1), "l"(srcXJ + koff));
            asm volatile("cp.async.cg.shared.global [%0], [%1], 16;" :: "r"(d2), "l"(srcYI + koff));
            asm volatile("cp.async.cg.shared.global [%0], [%1], 16;" :: "r"(d3), "l"(srcYJ + koff));
            asm volatile("cp.async.commit_group;");
        }

        const uint4* bxi = sbuf[st & 1][0];
        const uint4* bxj = sbuf[st & 1][1];
        const uint4* byi = sbuf[st & 1][2];
        const uint4* byj = sbuf[st & 1][3];

        #pragma unroll
        for (int kq = 0; kq < 8; kq++) {
            const int qi = kq ^ tik;
            const int qj = kq ^ tjk;
            {
                const uint4 u0 = bxi[(2 * ti    ) * 8 + qi];
                const uint4 u1 = bxi[(2 * ti + 1) * 8 + qi];
                const uint4 v0 = bxj[(2 * tj    ) * 8 + qj];
                const uint4 v1 = bxj[(2 * tj + 1) * 8 + qj];
                hx00 = acc8(hx00, u0, v0);  hx01 = acc8(hx01, u0, v1);
                hx10 = acc8(hx10, u1, v0);  hx11 = acc8(hx11, u1, v1);
            }
            {
                const uint4 u0 = byi[(2 * ti    ) * 8 + qi];
                const uint4 u1 = byi[(2 * ti + 1) * 8 + qi];
                const uint4 v0 = byj[(2 * tj    ) * 8 + qj];
                const uint4 v1 = byj[(2 * tj + 1) * 8 + qj];
                hy00 = acc8(hy00, u0, v0);  hy01 = acc8(hy01, u0, v1);
                hy10 = acc8(hy10, u1, v0);  hy11 = acc8(hy11, u1, v1);
            }
        }

        // drain fp16 accumulators into f32 each stage (bounds rounding error)
        fx00 += drain(hx00); hx00 = hz;   fx01 += drain(hx01); hx01 = hz;
        fx10 += drain(hx10); hx10 = hz;   fx11 += drain(hx11); hx11 = hz;
        fy00 += drain(hy00); hy00 = hz;   fy01 += drain(hy01); hy01 = hz;
        fy10 += drain(hy10); hy10 = hz;   fy11 += drain(hy11); hy11 = hz;
    }

    float4* gp = g_part + ((size_t)pt * KSPLIT + kc) * (TILE * (TILE / 2));
    gp[(2 * ti    ) * 16 + tj] = make_float4(fx00, fy00, fx01, fy01);
    gp[(2 * ti + 1) * 16 + tj] = make_float4(fx10, fy10, fx11, fy11);
}

// ---------- E1F: per-tile epilogue + fused final combine ----------
__global__ void e1f_kernel(float* __restrict__ out)
{
    __shared__ float sp[TILE][TILE + 1];
    __shared__ bool is_last;

    const int pt = blockIdx.x;
    const int bi = c_bi[pt], bj = c_bj[pt];
    const int t = threadIdx.x;
    const float4* gpt = g_part + (size_t)pt * KSPLIT * (TILE * (TILE / 2));

    #pragma unroll
    for (int half = 0; half < 2; half++) {
        const int item = t + 256 * half;
        const int r  = item >> 4;
        const int cp = item & 15;
        const int ig = bi * TILE + r;
        const int j0 = bj * TILE + 2 * cp;

        const float4* gp = gpt + r * 16 + cp;
        float4 m = make_float4(0.f, 0.f, 0.f, 0.f);
        #pragma unroll
        for (int kcc = 0; kcc < KSPLIT; kcc++) {
            const float4 v = gp[(size_t)kcc * (TILE * (TILE / 2))];
            m.x += v.x; m.y += v.y; m.z += v.z; m.w += v.w;
        }
        const float Sxi = g_Sx[ig], Syi = g_Sy[ig];
        const float sx0 = 2.0f * m.x - Sxi - g_Sx[j0];
        const float sy0 = 2.0f * m.y - Syi - g_Sy[j0];
        const float sx1 = 2.0f * m.z - Sxi - g_Sx[j0 + 1];
        const float sy1 = 2.0f * m.w - Syi - g_Sy[j0 + 1];
        const float p0 = sx0 * sy0;
        const float p1 = sx1 * sy1;

        sp[r][2 * cp]     = p0;
        sp[r][2 * cp + 1] = p1;

        float rs = p0 + p1;
        #pragma unroll
        for (int off = 8; off > 0; off >>= 1)
            rs += __shfl_xor_sync(0xffffffffu, rs, off);
        if (cp == 0)
            g_final[ig * NT + bj] = rs;
    }
    __syncthreads();

    if (t < TILE) {
        float cs = 0.f;
        #pragma unroll
        for (int rr = 0; rr < TILE; rr++) cs += sp[rr][t];
        g_colpart[pt * TILE + t] = cs;
    }

    // arrival counter: last CTA performs the final combine
    __threadfence();
    __syncthreads();
    if (t == 0) {
        const unsigned int ticket = atomicAdd(&g_cnt, 1u);
        is_last = (ticket == NPT - 1);
    }
    __syncthreads();
    if (!is_last) return;

    {
        const int i  = t;              // 256 threads
        const int tb = i >> 5;
        const int c  = i & 31;
        float s = 0.f;
        #pragma unroll
        for (int t2 = 0; t2 < NT; t2++)
            if (t2 >= tb) s += __ldcg(&g_final[i * NT + t2]);
        for (int a = 0; a < tb; a++) {
            const int ptc = a * NT - (a * (a - 1)) / 2 + (tb - a);
            s += __ldcg(&g_colpart[ptc * TILE + c]);
        }
        out[i] = -s * (1.0f / ((float)DD * (float)DD));
    }
    __syncthreads();
    if (t == 0) g_cnt = 0;             // reset for next graph replay
}

extern "C" void kernel_launch(void* const* d_in, const int* in_sizes, int n_in,
                              void* d_out, int out_size)
{
    const float* x = (const float*)d_in[0];
    const float* y = (const float*)d_in[1];
    float* out = (float*)d_out;

    conv_kernel<<<BB, 128>>>(x, y);
    pa_kernel<<<NPT * KSPLIT, 256>>>();
    e1f_kernel<<<NPT, 256>>>(out);
}

// round 9
// speedup vs baseline: 1.5572x; 1.0374x over previous
#include <cuda_runtime.h>
#include <cuda_fp16.h>
#include <cstdint>

// PairwiseL1Loss: x,y [256][4096] fp32.
// out[i] = -(1/D^2) * sum_j (sum_k|x_i-x_j|) * (sum_k|y_i-y_j|)
// Identity (on fp16-rounded values, S from the same rounded values):
//   sum_k|x_i-x_j| = 2*sum_k max(x_ik,x_jk) - S_i - S_j.
//
// CONV: fp32 -> fp16 copies + row sums. grid 512 (256 x-rows, 256 y-rows).
// PA  : 32x32 pair tiles, upper-tri (36), k-split x16 -> grid 576, occ 4.
//       cp.async double-buffered fp16 staging, __hmax2/__hadd2 math.
//       FUSED epilogue: per-tile last-block does tile reduction; global
//       last-block does final combine. 2 launches total.

#define BB 256
#define DD 4096
#define TILE 32
#define NT (BB / TILE)                 // 8
#define NPT 36                         // upper-tri tiles
#define KSPLIT 16
#define KPER (DD / KSPLIT)             // 256
#define KC 64                          // halfs per stage row (128B)
#define NSTAGE (KPER / KC)             // 4

__device__ __half g_hx[BB * DD];       // 2MB
__device__ __half g_hy[BB * DD];       // 2MB
__device__ float4 g_part[NPT * KSPLIT * TILE * (TILE / 2)];   // ~4.7MB
__device__ float  g_final[BB * NT];
__device__ float  g_colpart[NPT * TILE];
__device__ float  g_Sx[BB];
__device__ float  g_Sy[BB];
__device__ unsigned int g_tilecnt[NPT];   // zero-init
__device__ unsigned int g_cnt = 0;

__constant__ int c_bi[NPT] = {0,0,0,0,0,0,0,0, 1,1,1,1,1,1,1, 2,2,2,2,2,2,
                              3,3,3,3,3, 4,4,4,4, 5,5,5, 6,6, 7};
__constant__ int c_bj[NPT] = {0,1,2,3,4,5,6,7, 1,2,3,4,5,6,7, 2,3,4,5,6,7,
                              3,4,5,6,7, 4,5,6,7, 5,6,7, 6,7, 7};

// acc += sum of 4 half2 maxes of 8-half vectors u,v  (4 HMNMX2 + 4 HADD2)
__device__ __forceinline__ __half2 acc8(__half2 acc, const uint4 u, const uint4 v)
{
    const __half2* a = (const __half2*)&u;
    const __half2* b = (const __half2*)&v;
    const __half2 m0 = __hmax2(a[0], b[0]);
    const __half2 m1 = __hmax2(a[1], b[1]);
    const __half2 m2 = __hmax2(a[2], b[2]);
    const __half2 m3 = __hmax2(a[3], b[3]);
    return __hadd2(acc, __hadd2(__hadd2(m0, m1), __hadd2(m2, m3)));
}

__device__ __forceinline__ float drain(__half2 h)
{
    const float2 f = __half22float2(h);
    return f.x + f.y;
}

// ---------- CONV ----------
__global__ void conv_kernel(const float* __restrict__ x,
                            const float* __restrict__ y)
{
    const int bid = blockIdx.x;            // 0..511
    const int row = bid & (BB - 1);
    const bool isY = bid >= BB;
    const int tid = threadIdx.x;           // 256
    const float4* src = (const float4*)((isY ? y : x) + (size_t)row * DD);
    uint2* dst = (uint2*)((isY ? g_hy : g_hx) + (size_t)row * DD);

    float s = 0.f;
    #pragma unroll
    for (int it = 0; it < DD / 4 / 256; it++) {
        const int v = tid + 256 * it;
        const float4 a = src[v];
        const __half2 h0 = __floats2half2_rn(a.x, a.y);
        const __half2 h1 = __floats2half2_rn(a.z, a.w);
        uint2 u;
        u.x = *(const unsigned*)&h0;
        u.y = *(const unsigned*)&h1;
        dst[v] = u;
        s += drain(h0) + drain(h1);
    }
    #pragma unroll
    for (int off = 16; off > 0; off >>= 1)
        s += __shfl_xor_sync(0xffffffffu, s, off);
    __shared__ float ws[8];
    if ((tid & 31) == 0) ws[tid >> 5] = s;
    __syncthreads();
    if (tid == 0) {
        float t = 0.f;
        #pragma unroll
        for (int w = 0; w < 8; w++) t += ws[w];
        (isY ? g_Sy : g_Sx)[row] = t;
    }
}

// ---------- PA (+ fused epilogue) ----------
__global__ __launch_bounds__(256, 4)
void pa_kernel(float* __restrict__ out)
{
    __shared__ uint4 sbuf[2][4][TILE * 8];     // 32KB
    __shared__ float sp[TILE][TILE + 1];       // 4.2KB (tail)
    __shared__ unsigned int s_ticket;

    const int pt = blockIdx.x / KSPLIT;
    const int kc = blockIdx.x % KSPLIT;
    const int bi = c_bi[pt], bj = c_bj[pt];
    const int tid = threadIdx.x;
    const int ti = tid >> 4;
    const int tj = tid & 15;
    const int tik = ti & 7;
    const int tjk = tj & 7;

    const int sr = tid >> 3;
    const int sq = tid & 7;
    const int ssw = sr * 8 + (sq ^ ((sr >> 1) & 7));

    const __half* srcXI = g_hx + (size_t)(bi * TILE + sr) * DD + kc * KPER + sq * 8;
    const __half* srcXJ = g_hx + (size_t)(bj * TILE + sr) * DD + kc * KPER + sq * 8;
    const __half* srcYI = g_hy + (size_t)(bi * TILE + sr) * DD + kc * KPER + sq * 8;
    const __half* srcYJ = g_hy + (size_t)(bj * TILE + sr) * DD + kc * KPER + sq * 8;

    const __half2 hz = __floats2half2_rn(0.f, 0.f);
    __half2 hx00 = hz, hx01 = hz, hx10 = hz, hx11 = hz;
    __half2 hy00 = hz, hy01 = hz, hy10 = hz, hy11 = hz;
    float fx00 = 0.f, fx01 = 0.f, fx10 = 0.f, fx11 = 0.f;
    float fy00 = 0.f, fy01 = 0.f, fy10 = 0.f, fy11 = 0.f;

    {
        const uint32_t d0 = (uint32_t)__cvta_generic_to_shared(&sbuf[0][0][ssw]);
        const uint32_t d1 = (uint32_t)__cvta_generic_to_shared(&sbuf[0][1][ssw]);
        const uint32_t d2 = (uint32_t)__cvta_generic_to_shared(&sbuf[0][2][ssw]);
        const uint32_t d3 = (uint32_t)__cvta_generic_to_shared(&sbuf[0][3][ssw]);
        asm volatile("cp.async.cg.shared.global [%0], [%1], 16;" :: "r"(d0), "l"(srcXI));
        asm volatile("cp.async.cg.shared.global [%0], [%1], 16;" :: "r"(d1), "l"(srcXJ));
        asm volatile("cp.async.cg.shared.global [%0], [%1], 16;" :: "r"(d2), "l"(srcYI));
        asm volatile("cp.async.cg.shared.global [%0], [%1], 16;" :: "r"(d3), "l"(srcYJ));
        asm volatile("cp.async.commit_group;");
    }

    #pragma unroll
    for (int st = 0; st < NSTAGE; st++) {
        asm volatile("cp.async.wait_group 0;");
        __syncthreads();

        if (st + 1 < NSTAGE) {
            const int nb = (st + 1) & 1;
            const int koff = (st + 1) * KC;
            const uint32_t d0 = (uint32_t)__cvta_generic_to_shared(&sbuf[nb][0][ssw]);
            const uint32_t d1 = (uint32_t)__cvta_generic_to_shared(&sbuf[nb][1][ssw]);
            const uint32_t d2 = (uint32_t)__cvta_generic_to_shared(&sbuf[nb][2][ssw]);
            const uint32_t d3 = (uint32_t)__cvta_generic_to_shared(&sbuf[nb][3][ssw]);
            asm volatile("cp.async.cg.shared.global [%0], [%1], 16;" :: "r"(d0), "l"(srcXI + koff));
            asm volatile("cp.async.cg.shared.global [%0], [%1], 16;" :: "r"(d1), "l"(srcXJ + koff));
            asm volatile("cp.async.cg.shared.global [%0], [%1], 16;" :: "r"(d2), "l"(srcYI + koff));
            asm volatile("cp.async.cg.shared.global [%0], [%1], 16;" :: "r"(d3), "l"(srcYJ + koff));
            asm volatile("cp.async.commit_group;");
        }

        const uint4* bxi = sbuf[st & 1][0];
        const uint4* bxj = sbuf[st & 1][1];
        const uint4* byi = sbuf[st & 1][2];
        const uint4* byj = sbuf[st & 1][3];

        #pragma unroll
        for (int kq = 0; kq < 8; kq++) {
            const int qi = kq ^ tik;
            const int qj = kq ^ tjk;
            {
                const uint4 u0 = bxi[(2 * ti    ) * 8 + qi];
                const uint4 u1 = bxi[(2 * ti + 1) * 8 + qi];
                const uint4 v0 = bxj[(2 * tj    ) * 8 + qj];
                const uint4 v1 = bxj[(2 * tj + 1) * 8 + qj];
                hx00 = acc8(hx00, u0, v0);  hx01 = acc8(hx01, u0, v1);
                hx10 = acc8(hx10, u1, v0);  hx11 = acc8(hx11, u1, v1);
            }
            {
                const uint4 u0 = byi[(2 * ti    ) * 8 + qi];
                const uint4 u1 = byi[(2 * ti + 1) * 8 + qi];
                const uint4 v0 = byj[(2 * tj    ) * 8 + qj];
                const uint4 v1 = byj[(2 * tj + 1) * 8 + qj];
                hy00 = acc8(hy00, u0, v0);  hy01 = acc8(hy01, u0, v1);
                hy10 = acc8(hy10, u1, v0);  hy11 = acc8(hy11, u1, v1);
            }
        }

        fx00 += drain(hx00); hx00 = hz;   fx01 += drain(hx01); hx01 = hz;
        fx10 += drain(hx10); hx10 = hz;   fx11 += drain(hx11); hx11 = hz;
        fy00 += drain(hy00); hy00 = hz;   fy01 += drain(hy01); hy01 = hz;
        fy10 += drain(hy10); hy10 = hz;   fy11 += drain(hy11); hy11 = hz;
    }

    float4* gp = g_part + ((size_t)pt * KSPLIT + kc) * (TILE * (TILE / 2));
    gp[(2 * ti    ) * 16 + tj] = make_float4(fx00, fy00, fx01, fy01);
    gp[(2 * ti + 1) * 16 + tj] = make_float4(fx10, fy10, fx11, fy11);

    // ---- per-tile last-block election ----
    __threadfence();
    __syncthreads();
    if (tid == 0) s_ticket = atomicAdd(&g_tilecnt[pt], 1u);
    __syncthreads();
    if (s_ticket != KSPLIT - 1) return;
    if (tid == 0) g_tilecnt[pt] = 0;       // reset for next replay

    // ---- tile epilogue (ex-e1 body), reads via L2 ----
    const float4* gpt = (const float4*)(g_part + (size_t)pt * KSPLIT * (TILE * (TILE / 2)));
    #pragma unroll
    for (int half = 0; half < 2; half++) {
        const int item = tid + 256 * half;
        const int r  = item >> 4;
        const int cp = item & 15;
        const int ig = bi * TILE + r;
        const int j0 = bj * TILE + 2 * cp;

        const float4* gpr = gpt + r * 16 + cp;
        float4 m = make_float4(0.f, 0.f, 0.f, 0.f);
        #pragma unroll
        for (int kcc = 0; kcc < KSPLIT; kcc++) {
            const float4 v = __ldcg(gpr + (size_t)kcc * (TILE * (TILE / 2)));
            m.x += v.x; m.y += v.y; m.z += v.z; m.w += v.w;
        }
        const float Sxi = g_Sx[ig], Syi = g_Sy[ig];
        const float sx0 = 2.0f * m.x - Sxi - g_Sx[j0];
        const float sy0 = 2.0f * m.y - Syi - g_Sy[j0];
        const float sx1 = 2.0f * m.z - Sxi - g_Sx[j0 + 1];
        const float sy1 = 2.0f * m.w - Syi - g_Sy[j0 + 1];
        const float p0 = sx0 * sy0;
        const float p1 = sx1 * sy1;

        sp[r][2 * cp]     = p0;
        sp[r][2 * cp + 1] = p1;

        float rs = p0 + p1;
        #pragma unroll
        for (int off = 8; off > 0; off >>= 1)
            rs += __shfl_xor_sync(0xffffffffu, rs, off);
        if (cp == 0)
            g_final[ig * NT + bj] = rs;
    }
    __syncthreads();

    if (tid < TILE) {
        float cs = 0.f;
        #pragma unroll
        for (int rr = 0; rr < TILE; rr++) cs += sp[rr][tid];
        g_colpart[pt * TILE + tid] = cs;
    }

    // ---- global last-tile election ----
    __threadfence();
    __syncthreads();
    if (tid == 0) s_ticket = atomicAdd(&g_cnt, 1u);
    __syncthreads();
    if (s_ticket != NPT - 1) return;

    {
        const int i  = tid;                // 256 threads
        const int tb = i >> 5;
        const int c  = i & 31;
        float s = 0.f;
        #pragma unroll
        for (int t2 = 0; t2 < NT; t2++)
            if (t2 >= tb) s += __ldcg(&g_final[i * NT + t2]);
        for (int a = 0; a < tb; a++) {
            const int ptc = a * NT - (a * (a - 1)) / 2 + (tb - a);
            s += __ldcg(&g_colpart[ptc * TILE + c]);
        }
        out[i] = -s * (1.0f / ((float)DD * (float)DD));
    }
    __syncthreads();
    if (tid == 0) g_cnt = 0;               // reset for next replay
}

extern "C" void kernel_launch(void* const* d_in, const int* in_sizes, int n_in,
                              void* d_out, int out_size)
{
    const float* x = (const float*)d_in[0];
    const float* y = (const float*)d_in[1];
    float* out = (float*)d_out;

    conv_kernel<<<2 * BB, 256>>>(x, y);
    pa_kernel<<<NPT * KSPLIT, 256>>>(out);
}